// round 14
// baseline (speedup 1.0000x reference)
#include <cuda_runtime.h>
#include <cuda_fp16.h>
#include <cstdint>

// ---------------------------------------------------------------------------
// Problem constants
// ---------------------------------------------------------------------------
#define M_DIM 4096
#define N_DIM 11008
#define K_DIM 4096
#define GROUP 128

#define BM 128            // CTA M tile
#define BN 256            // CTA N tile (full tiles)
#define KC 64             // K halves per pipeline chunk (= 128 bytes per row)
#define NKC (K_DIM / KC)  // 64 chunks
#define NMT (M_DIM / BM)  // 32
#define NNT (N_DIM / BN)  // 43

#define A_BLK_BYTES (BM * 128)       // 16384
#define B_BLK_BYTES (BN * 128)       // 32768
#define STAGE_BYTES (A_BLK_BYTES + B_BLK_BYTES)  // 49152
#define NSTAGES 4
#define SM_TOTAL (2048 + NSTAGES * STAGE_BYTES)  // 198656

// Wave-quantization split: 1332 full tiles (9 exact waves of 148) + the last
// 44 tiles split into 88 N-halves forming a short final wave.
#define FULL_CTAS 1332
#define GRID_CTAS (FULL_CTAS + 88)   // 1420

// Dequant: kc-major, 344 blocks per kc (88064 uint4 per kc / 256 threads).
#define DQ_BLOCKS_PER_KC 344
#define DQ_BLOCKS (DQ_BLOCKS_PER_KC * NKC)   // 22016
#define TX_BLOCKS (M_DIM * 16 / 8)           // 8192

// Tiled+swizzled scratch in GMEM
__device__ uint4 g_A[(size_t)NMT * NKC * A_BLK_BYTES / 16];   // 33.5 MB
__device__ uint4 g_B[(size_t)NNT * NKC * B_BLK_BYTES / 16];   // 90.2 MB
__device__ int   g_cnt[NKC];                                  // per-kc dequant counters

__host__ __device__ __forceinline__ uint32_t swz128(uint32_t off) {
    return off ^ ((off >> 3) & 0x70u);
}

// ---------------------------------------------------------------------------
// PTX helpers (sm_90-level only; tcgen05 NOT available in this build path)
// ---------------------------------------------------------------------------
__device__ __forceinline__ uint32_t smem_u32(const void* p) {
    uint32_t a;
    asm("{ .reg .u64 t; cvta.to.shared.u64 t, %1; cvt.u32.u64 %0, t; }" : "=r"(a) : "l"(p));
    return a;
}

#define MBAR_INIT(addr, cnt) \
    asm volatile("mbarrier.init.shared.b64 [%0], %1;" :: "r"(addr), "r"(cnt) : "memory")

#define MBAR_EXPECT_TX(addr, bytes) \
    asm volatile("mbarrier.arrive.expect_tx.shared.b64 _, [%0], %1;" :: "r"(addr), "r"(bytes) : "memory")

#define MBAR_ARRIVE(addr) \
    asm volatile("mbarrier.arrive.shared.b64 _, [%0];" :: "r"(addr) : "memory")

#define MBAR_WAIT(addr, parity) do {                                        \
    uint32_t _m = (addr); uint32_t _p = (parity); uint32_t _d;              \
    asm volatile("{\n\t.reg .pred p;\n\t"                                   \
        "mbarrier.try_wait.parity.acquire.cta.shared::cta.b64 p, [%1], %2;\n\t" \
        "selp.b32 %0, 1, 0, p;\n\t}"                                        \
        : "=r"(_d) : "r"(_m), "r"(_p) : "memory");                          \
    if (!_d) {                                                              \
        asm volatile("{\n\t.reg .pred P1;\n\t"                              \
            "W0_%=:\n\t"                                                    \
            "mbarrier.try_wait.parity.acquire.cta.shared::cta.b64 P1, [%0], %1, 0x989680;\n\t" \
            "@P1 bra.uni W1_%=;\n\t"                                        \
            "bra.uni W0_%=;\n\t"                                            \
            "W1_%=:\n\t}" :: "r"(_m), "r"(_p) : "memory");                  \
    }                                                                       \
} while (0)

__device__ __forceinline__ void bulk_ld(uint32_t dst, const void* src, uint32_t bytes,
                                        uint32_t mbar) {
    asm volatile(
        "cp.async.bulk.shared::cluster.global.mbarrier::complete_tx::bytes [%0], [%1], %2, [%3];"
        :: "r"(dst), "l"(src), "r"(bytes), "r"(mbar) : "memory");
}

__device__ __forceinline__ void ldsm4(uint32_t* r, uint32_t addr) {
    asm volatile("ldmatrix.sync.aligned.m8n8.x4.shared.b16 {%0,%1,%2,%3}, [%4];\n"
                 : "=r"(r[0]), "=r"(r[1]), "=r"(r[2]), "=r"(r[3]) : "r"(addr));
}
__device__ __forceinline__ void mma16816(float* c, const uint32_t* a, uint32_t b0, uint32_t b1) {
    asm volatile(
        "mma.sync.aligned.m16n8k16.row.col.f32.f16.f16.f32 "
        "{%0,%1,%2,%3}, {%4,%5,%6,%7}, {%8,%9}, {%0,%1,%2,%3};\n"
        : "+f"(c[0]), "+f"(c[1]), "+f"(c[2]), "+f"(c[3])
        : "r"(a[0]), "r"(a[1]), "r"(a[2]), "r"(a[3]), "r"(b0), "r"(b1));
}

// ---------------------------------------------------------------------------
// Kernel 0: reset the per-kc counters (runs on the side stream each call).
// ---------------------------------------------------------------------------
__global__ void reset_counters_kernel() {
    if (threadIdx.x < NKC) g_cnt[threadIdx.x] = 0;
}

// ---------------------------------------------------------------------------
// Kernel 1: x' = H (s2 * H (s1 * x)) / 128. 2 groups per warp (8 vals/lane).
// (byte-identical to round-10/13 winner)
// ---------------------------------------------------------------------------
__global__ __launch_bounds__(256) void transform_x_kernel(
    const float* __restrict__ x, const float* __restrict__ s1,
    const float* __restrict__ s2, unsigned char* __restrict__ At) {
    const int lane = threadIdx.x & 31;
    const int wrp = threadIdx.x >> 5;
    const int unit = blockIdx.x * 8 + wrp;   // 0 .. 65535
    const int row = unit >> 4;               // 4096 rows
    const int g0 = (unit & 15) * 2;          // groups g0, g0+1

    const float4 s1v = *(const float4*)(s1 + lane * 4);
    const float4 s2v = *(const float4*)(s2 + lane * 4);

    float v[8];
    {
        const float4 a = *(const float4*)(x + (size_t)row * K_DIM + g0 * GROUP + lane * 4);
        const float4 b = *(const float4*)(x + (size_t)row * K_DIM + (g0 + 1) * GROUP + lane * 4);
        v[0] = a.x * s1v.x; v[1] = a.y * s1v.y; v[2] = a.z * s1v.z; v[3] = a.w * s1v.w;
        v[4] = b.x * s1v.x; v[5] = b.y * s1v.y; v[6] = b.z * s1v.z; v[7] = b.w * s1v.w;
    }

#pragma unroll
    for (int pass = 0; pass < 2; pass++) {
#pragma unroll
        for (int h = 0; h < 2; h++) {
            float t0 = v[h*4+0] + v[h*4+1], t1 = v[h*4+0] - v[h*4+1];
            float t2 = v[h*4+2] + v[h*4+3], t3 = v[h*4+2] - v[h*4+3];
            v[h*4+0] = t0 + t2; v[h*4+2] = t0 - t2;
            v[h*4+1] = t1 + t3; v[h*4+3] = t1 - t3;
        }
#pragma unroll
        for (int xm = 1; xm <= 16; xm <<= 1) {
            bool hi = (lane & xm) != 0;
#pragma unroll
            for (int j = 0; j < 8; j++) {
                float o = __shfl_xor_sync(0xFFFFFFFFu, v[j], xm);
                v[j] = hi ? (o - v[j]) : (v[j] + o);
            }
        }
        if (pass == 0) {
            v[0] *= s2v.x; v[1] *= s2v.y; v[2] *= s2v.z; v[3] *= s2v.w;
            v[4] *= s2v.x; v[5] *= s2v.y; v[6] *= s2v.z; v[7] *= s2v.w;
        }
    }

    const float sc = 1.0f / 128.0f;
    const int mt = row >> 7, r = row & 127;
    const int e = 4 * lane;
#pragma unroll
    for (int h = 0; h < 2; h++) {
        __half2 h01 = __floats2half2_rn(v[h*4+0] * sc, v[h*4+1] * sc);
        __half2 h23 = __floats2half2_rn(v[h*4+2] * sc, v[h*4+3] * sc);
        const int grp = g0 + h;
        const int kc = grp * 2 + (e >> 6);
        const int c = e & 63;
        const size_t base = ((size_t)mt * NKC + kc) * A_BLK_BYTES;
        const uint32_t off = swz128((uint32_t)(r * 128 + c * 2));
        uint2 val = { *(uint32_t*)&h01, *(uint32_t*)&h23 };
        *(uint2*)(At + base + off) = val;
    }
}

// ---------------------------------------------------------------------------
// Kernel 2: dequant W, KC-MAJOR (runs concurrently with the GEMM on a side
// stream; publishes per-kc completion counters that the GEMM producer polls).
// Block b: kc = b / 344, covers 256 uint4 of that kc across rows.
// 8 threads share an output row -> 128B-contiguous loads and stores.
// ---------------------------------------------------------------------------
__global__ __launch_bounds__(256) void dequant_kernel(
    const uint4* __restrict__ pw4, const float* __restrict__ norms,
    const float* __restrict__ cent, unsigned char* __restrict__ Bt) {
    __shared__ float c[16];
    if (threadIdx.x < 16) c[threadIdx.x] = cent[threadIdx.x];
    __syncthreads();

    const int kc = blockIdx.x / DQ_BLOCKS_PER_KC;
    const int inner = blockIdx.x - kc * DQ_BLOCKS_PER_KC;
    const int u = inner * 256 + threadIdx.x;   // 0 .. 88063
    const int o = u >> 3;                      // output row
    const int ql = u & 7;                      // uint4 within this kc
    const int q = kc * 8 + ql;

    const uint4 w = pw4[(size_t)o * 512 + q];
    const float norm = __ldg(&norms[o * 32 + (q >> 4)]);

    __half2 h[4];
    h[0] = __floats2half2_rn(c[w.x & 15u] * norm, c[(w.x >> 4) & 15u] * norm);
    h[1] = __floats2half2_rn(c[w.y & 15u] * norm, c[(w.y >> 4) & 15u] * norm);
    h[2] = __floats2half2_rn(c[w.z & 15u] * norm, c[(w.z >> 4) & 15u] * norm);
    h[3] = __floats2half2_rn(c[w.w & 15u] * norm, c[(w.w >> 4) & 15u] * norm);

    const int nt = o >> 8, r = o & 255;
    const uint32_t off = swz128((uint32_t)(r * 128 + ql * 16));
    const size_t base = ((size_t)nt * NKC + kc) * B_BLK_BYTES;
    *(uint4*)(Bt + base + off) = *(uint4*)h;

    // publish: all of this block's stores, then bump the kc counter
    __syncthreads();
    if (threadIdx.x == 0) {
        __threadfence();
        atomicAdd(&g_cnt[kc], 1);
    }
}

// ---------------------------------------------------------------------------
// Kernel 3: mma.sync GEMM — mainloop BYTE-IDENTICAL to the round-10 winner.
// Only addition: the producer polls g_cnt[j] >= 344 before loading B chunk j
// (dequant runs concurrently on a side stream). Stale counters on graph
// replays are benign: B's contents are identical on every call.
// ---------------------------------------------------------------------------
extern __shared__ unsigned char dsm[];

template <int NBW>   // MMAs along N per warp: 8 (full) or 4 (half)
__device__ __forceinline__ void consume_tile(
    uint32_t sb, float* __restrict__ C, const float* __restrict__ bias,
    int bm, int bn, int wid, int lane) {
    const int wm = (wid >> 2) * 64;
    const int wn = (wid & 3) * (NBW * 8);

    float acc[4][NBW][4];
#pragma unroll
    for (int i = 0; i < 4; i++)
#pragma unroll
        for (int j = 0; j < NBW; j++)
#pragma unroll
            for (int k = 0; k < 4; k++) acc[i][j][k] = 0.0f;

    const int a_row = lane & 15;
    const int a_colh = (lane >> 4) * 8;
    const int b_row = (lane & 7) + (lane >> 4) * 8;
    const int b_colh = ((lane >> 3) & 1) * 8;

    for (int j = 0; j < NKC; j++) {
        const int s = j & 3;
        MBAR_WAIT(sb + 8 * s, (j >> 2) & 1);
        const uint32_t as = sb + 1024 + s * STAGE_BYTES;
        const uint32_t bs = as + A_BLK_BYTES;

#pragma unroll
        for (int ks = 0; ks < 4; ks++) {
            uint32_t afr[4][4];
#pragma unroll
            for (int m = 0; m < 4; m++)
                ldsm4(afr[m], as + swz128((uint32_t)((wm + m * 16 + a_row) * 128 +
                                                     (ks * 16 + a_colh) * 2)));
            uint32_t bfr[NBW / 2][4];
#pragma unroll
            for (int nb = 0; nb < NBW / 2; nb++)
                ldsm4(bfr[nb], bs + swz128((uint32_t)((wn + nb * 16 + b_row) * 128 +
                                                      (ks * 16 + b_colh) * 2)));
#pragma unroll
            for (int m = 0; m < 4; m++) {
#pragma unroll
                for (int n = 0; n < NBW; n++) {
                    mma16816(acc[m][n], afr[m], bfr[n >> 1][(n & 1) * 2],
                             bfr[n >> 1][(n & 1) * 2 + 1]);
                }
            }
        }
        if (lane == 0) MBAR_ARRIVE(sb + 32 + 8 * s);
    }

    // epilogue
    const int gid = lane >> 2;
    const int tq = lane & 3;
    float bz[NBW][2];
#pragma unroll
    for (int n = 0; n < NBW; n++) {
        const int col0 = bn + wn + n * 8 + tq * 2;
        bz[n][0] = __ldg(&bias[col0]);
        bz[n][1] = __ldg(&bias[col0 + 1]);
    }
#pragma unroll
    for (int m = 0; m < 4; m++) {
        const int row0 = bm + wm + m * 16 + gid;
#pragma unroll
        for (int n = 0; n < NBW; n++) {
            const int col0 = bn + wn + n * 8 + tq * 2;
            float2 v0 = { acc[m][n][0] + bz[n][0], acc[m][n][1] + bz[n][1] };
            float2 v1 = { acc[m][n][2] + bz[n][0], acc[m][n][3] + bz[n][1] };
            *(float2*)(C + (size_t)row0 * N_DIM + col0) = v0;
            *(float2*)(C + (size_t)(row0 + 8) * N_DIM + col0) = v1;
        }
    }
}

__global__ __launch_bounds__(288, 1) void gemm_kernel(
    const unsigned char* __restrict__ At, const unsigned char* __restrict__ Bt,
    const float* __restrict__ bias, float* __restrict__ C) {
    const int tid = threadIdx.x;
    const int wid = tid >> 5;
    const int lane = tid & 31;
    const uint32_t sb = (smem_u32(dsm) + 1023) & ~1023u;

    // id -> (mt, nt, half). nt-fastest order; last 44 tiles split into N-halves.
    const int id = blockIdx.x;
    int mt, nt, half;
    if (id < FULL_CTAS) {
        mt = id / NNT; nt = id - mt * NNT; half = -1;
    } else {
        const int k = id - FULL_CTAS;             // 0..87
        const int tile = FULL_CTAS + (k >> 1);    // 1332..1375
        mt = tile / NNT; nt = tile - mt * NNT; half = k & 1;
    }
    const unsigned char* Ag = At + (size_t)mt * NKC * A_BLK_BYTES;
    const unsigned char* Bg = Bt + (size_t)nt * NKC * B_BLK_BYTES +
                              (half > 0 ? 16384 : 0);
    const uint32_t bsz = (half < 0) ? 32768u : 16384u;
    const int bm = mt * BM;
    const int bn = nt * BN + (half > 0 ? 128 : 0);

    if (tid == 0) {
#pragma unroll
        for (int s = 0; s < NSTAGES; s++) {
            MBAR_INIT(sb + 8 * s, 1);       // full[s]
            MBAR_INIT(sb + 32 + 8 * s, 8);  // empty[s]
        }
        asm volatile("fence.proxy.async.shared::cta;" ::: "memory");
    }
    __syncthreads();

    if (wid == 8) {
        // ---------------- producer warp (lane 0 only) ----------------
        if (lane == 0) {
            for (int j = 0; j < NKC; j++) {
                const int s = j & 3;
                if (j >= NSTAGES) {
                    MBAR_WAIT(sb + 32 + 8 * s, ((j >> 2) - 1) & 1);
                }
                // gate on concurrent dequant: B chunk j ready when g_cnt[j]==344
                {
                    volatile int* cp = (volatile int*)&g_cnt[j];
                    if (*cp < DQ_BLOCKS_PER_KC) {
                        while (*cp < DQ_BLOCKS_PER_KC) { __nanosleep(128); }
                        asm volatile("fence.proxy.async;" ::: "memory");
                    }
                }
                const uint32_t full = sb + 8 * s;
                MBAR_EXPECT_TX(full, A_BLK_BYTES + bsz);
                const uint32_t st = sb + 1024 + s * STAGE_BYTES;
                bulk_ld(st, Ag + (size_t)j * A_BLK_BYTES, A_BLK_BYTES, full);
                bulk_ld(st + A_BLK_BYTES, Bg + (size_t)j * B_BLK_BYTES, bsz, full);
            }
        }
        return;
    }

    if (half < 0) consume_tile<8>(sb, C, bias, bm, bn, wid, lane);
    else          consume_tile<4>(sb, C, bias, bm, bn, wid, lane);
}

// ---------------------------------------------------------------------------
// Launch: fork/join so dequant (side stream) overlaps transform + GEMM start.
//   stream 0 : transform_x ───────────── gemm ──── waits evJ
//   stream s2: (waits evF) reset → dequant → evJ
// ---------------------------------------------------------------------------
extern "C" void kernel_launch(void* const* d_in, const int* in_sizes, int n_in,
                              void* d_out, int out_size) {
    const float* x     = (const float*)d_in[0];
    const uint4* pw4   = (const uint4*)d_in[1];
    const float* norms = (const float*)d_in[2];
    const float* cent  = (const float*)d_in[3];
    const float* s1    = (const float*)d_in[4];
    const float* s2v   = (const float*)d_in[5];
    const float* bias  = (const float*)d_in[6];
    float* out = (float*)d_out;

    unsigned char *At, *Bt;
    cudaGetSymbolAddress((void**)&At, g_A);
    cudaGetSymbolAddress((void**)&Bt, g_B);

    static cudaStream_t s2 = nullptr;
    static cudaEvent_t evF = nullptr, evJ = nullptr;
    if (s2 == nullptr) {
        cudaStreamCreateWithFlags(&s2, cudaStreamNonBlocking);
        cudaEventCreateWithFlags(&evF, cudaEventDisableTiming);
        cudaEventCreateWithFlags(&evJ, cudaEventDisableTiming);
        cudaFuncSetAttribute(gemm_kernel, cudaFuncAttributeMaxDynamicSharedMemorySize,
                             SM_TOTAL);
    }

    // fork side branch
    cudaEventRecord(evF, 0);
    cudaStreamWaitEvent(s2, evF, 0);
    reset_counters_kernel<<<1, 64, 0, s2>>>();
    dequant_kernel<<<DQ_BLOCKS, 256, 0, s2>>>(pw4, norms, cent, Bt);
    cudaEventRecord(evJ, s2);

    // main branch
    transform_x_kernel<<<TX_BLOCKS, 256>>>(x, s1, s2v, At);
    gemm_kernel<<<GRID_CTAS, 288, SM_TOTAL>>>(At, Bt, bias, out);

    // join
    cudaStreamWaitEvent(0, evJ, 0);
}

// round 15
// speedup vs baseline: 1.0143x; 1.0143x over previous
#include <cuda_runtime.h>
#include <cuda_fp16.h>
#include <cstdint>

// ---------------------------------------------------------------------------
// Problem constants
// ---------------------------------------------------------------------------
#define M_DIM 4096
#define N_DIM 11008
#define K_DIM 4096
#define GROUP 128

#define BM 128            // CTA M tile
#define BN 256            // CTA N tile (full tiles)
#define KC 64             // K halves per pipeline chunk (= 128 bytes per row)
#define NKC (K_DIM / KC)  // 64 chunks
#define NMT (M_DIM / BM)  // 32
#define NNT (N_DIM / BN)  // 43

#define A_BLK_BYTES (BM * 128)       // 16384
#define B_BLK_BYTES (BN * 128)       // 32768
#define STAGE_BYTES (A_BLK_BYTES + B_BLK_BYTES)  // 49152
#define NSTAGES 4
#define SM_TOTAL (2048 + NSTAGES * STAGE_BYTES)  // 198656

// Wave-quantization split: 1332 full tiles (9 exact waves of 148) + the last
// 44 tiles split into 88 N-halves forming a short final wave.
#define FULL_CTAS 1332
#define GRID_CTAS (FULL_CTAS + 88)   // 1420

#define DQ_BLOCKS (N_DIM * 512 / 256)     // 22016
#define TX_BLOCKS (M_DIM * 16 / 8)        // 8192

// Tiled+swizzled scratch in GMEM
__device__ uint4 g_A[(size_t)NMT * NKC * A_BLK_BYTES / 16];   // 33.5 MB
__device__ uint4 g_B[(size_t)NNT * NKC * B_BLK_BYTES / 16];   // 90.2 MB

__host__ __device__ __forceinline__ uint32_t swz128(uint32_t off) {
    return off ^ ((off >> 3) & 0x70u);
}

// ---------------------------------------------------------------------------
// PTX helpers (sm_90-level only; tcgen05 NOT available in this build path)
// ---------------------------------------------------------------------------
__device__ __forceinline__ uint32_t smem_u32(const void* p) {
    uint32_t a;
    asm("{ .reg .u64 t; cvta.to.shared.u64 t, %1; cvt.u32.u64 %0, t; }" : "=r"(a) : "l"(p));
    return a;
}

#define MBAR_INIT(addr, cnt) \
    asm volatile("mbarrier.init.shared.b64 [%0], %1;" :: "r"(addr), "r"(cnt) : "memory")

#define MBAR_EXPECT_TX(addr, bytes) \
    asm volatile("mbarrier.arrive.expect_tx.shared.b64 _, [%0], %1;" :: "r"(addr), "r"(bytes) : "memory")

#define MBAR_ARRIVE(addr) \
    asm volatile("mbarrier.arrive.shared.b64 _, [%0];" :: "r"(addr) : "memory")

#define MBAR_WAIT(addr, parity) do {                                        \
    uint32_t _m = (addr); uint32_t _p = (parity); uint32_t _d;              \
    asm volatile("{\n\t.reg .pred p;\n\t"                                   \
        "mbarrier.try_wait.parity.acquire.cta.shared::cta.b64 p, [%1], %2;\n\t" \
        "selp.b32 %0, 1, 0, p;\n\t}"                                        \
        : "=r"(_d) : "r"(_m), "r"(_p) : "memory");                          \
    if (!_d) {                                                              \
        asm volatile("{\n\t.reg .pred P1;\n\t"                              \
            "W0_%=:\n\t"                                                    \
            "mbarrier.try_wait.parity.acquire.cta.shared::cta.b64 P1, [%0], %1, 0x989680;\n\t" \
            "@P1 bra.uni W1_%=;\n\t"                                        \
            "bra.uni W0_%=;\n\t"                                            \
            "W1_%=:\n\t}" :: "r"(_m), "r"(_p) : "memory");                  \
    }                                                                       \
} while (0)

__device__ __forceinline__ void bulk_ld(uint32_t dst, const void* src, uint32_t bytes,
                                        uint32_t mbar) {
    asm volatile(
        "cp.async.bulk.shared::cluster.global.mbarrier::complete_tx::bytes [%0], [%1], %2, [%3];"
        :: "r"(dst), "l"(src), "r"(bytes), "r"(mbar) : "memory");
}

__device__ __forceinline__ void ldsm4(uint32_t* r, uint32_t addr) {
    asm volatile("ldmatrix.sync.aligned.m8n8.x4.shared.b16 {%0,%1,%2,%3}, [%4];\n"
                 : "=r"(r[0]), "=r"(r[1]), "=r"(r[2]), "=r"(r[3]) : "r"(addr));
}
__device__ __forceinline__ void mma16816(float* c, const uint32_t* a, uint32_t b0, uint32_t b1) {
    asm volatile(
        "mma.sync.aligned.m16n8k16.row.col.f32.f16.f16.f32 "
        "{%0,%1,%2,%3}, {%4,%5,%6,%7}, {%8,%9}, {%0,%1,%2,%3};\n"
        : "+f"(c[0]), "+f"(c[1]), "+f"(c[2]), "+f"(c[3])
        : "r"(a[0]), "r"(a[1]), "r"(a[2]), "r"(a[3]), "r"(b0), "r"(b1));
}

// ---------------------------------------------------------------------------
// Kernel 1: x' = H (s2 * H (s1 * x)) / 128. 2 groups per warp (8 vals/lane).
// (byte-identical to round-10 winner)
// ---------------------------------------------------------------------------
__global__ __launch_bounds__(256) void transform_x_kernel(
    const float* __restrict__ x, const float* __restrict__ s1,
    const float* __restrict__ s2, unsigned char* __restrict__ At) {
    const int lane = threadIdx.x & 31;
    const int wrp = threadIdx.x >> 5;
    const int unit = blockIdx.x * 8 + wrp;   // 0 .. 65535
    const int row = unit >> 4;               // 4096 rows
    const int g0 = (unit & 15) * 2;          // groups g0, g0+1

    const float4 s1v = *(const float4*)(s1 + lane * 4);
    const float4 s2v = *(const float4*)(s2 + lane * 4);

    float v[8];
    {
        const float4 a = *(const float4*)(x + (size_t)row * K_DIM + g0 * GROUP + lane * 4);
        const float4 b = *(const float4*)(x + (size_t)row * K_DIM + (g0 + 1) * GROUP + lane * 4);
        v[0] = a.x * s1v.x; v[1] = a.y * s1v.y; v[2] = a.z * s1v.z; v[3] = a.w * s1v.w;
        v[4] = b.x * s1v.x; v[5] = b.y * s1v.y; v[6] = b.z * s1v.z; v[7] = b.w * s1v.w;
    }

#pragma unroll
    for (int pass = 0; pass < 2; pass++) {
#pragma unroll
        for (int h = 0; h < 2; h++) {
            float t0 = v[h*4+0] + v[h*4+1], t1 = v[h*4+0] - v[h*4+1];
            float t2 = v[h*4+2] + v[h*4+3], t3 = v[h*4+2] - v[h*4+3];
            v[h*4+0] = t0 + t2; v[h*4+2] = t0 - t2;
            v[h*4+1] = t1 + t3; v[h*4+3] = t1 - t3;
        }
#pragma unroll
        for (int xm = 1; xm <= 16; xm <<= 1) {
            bool hi = (lane & xm) != 0;
#pragma unroll
            for (int j = 0; j < 8; j++) {
                float o = __shfl_xor_sync(0xFFFFFFFFu, v[j], xm);
                v[j] = hi ? (o - v[j]) : (v[j] + o);
            }
        }
        if (pass == 0) {
            v[0] *= s2v.x; v[1] *= s2v.y; v[2] *= s2v.z; v[3] *= s2v.w;
            v[4] *= s2v.x; v[5] *= s2v.y; v[6] *= s2v.z; v[7] *= s2v.w;
        }
    }

    const float sc = 1.0f / 128.0f;
    const int mt = row >> 7, r = row & 127;
    const int e = 4 * lane;
#pragma unroll
    for (int h = 0; h < 2; h++) {
        __half2 h01 = __floats2half2_rn(v[h*4+0] * sc, v[h*4+1] * sc);
        __half2 h23 = __floats2half2_rn(v[h*4+2] * sc, v[h*4+3] * sc);
        const int grp = g0 + h;
        const int kc = grp * 2 + (e >> 6);
        const int c = e & 63;
        const size_t base = ((size_t)mt * NKC + kc) * A_BLK_BYTES;
        const uint32_t off = swz128((uint32_t)(r * 128 + c * 2));
        uint2 val = { *(uint32_t*)&h01, *(uint32_t*)&h23 };
        *(uint2*)(At + base + off) = val;
    }
}

// ---------------------------------------------------------------------------
// Kernel 2: dequant W -> tiled swizzled layout (vectorized, 256-row B tiles).
// (byte-identical to round-10 winner)
// ---------------------------------------------------------------------------
__global__ __launch_bounds__(256) void dequant_kernel(
    const uint4* __restrict__ pw4, const float* __restrict__ norms,
    const float* __restrict__ cent, unsigned char* __restrict__ Bt) {
    __shared__ float c[16];
    if (threadIdx.x < 16) c[threadIdx.x] = cent[threadIdx.x];
    __syncthreads();

    const int idx = blockIdx.x * 256 + threadIdx.x;  // 0 .. 11008*512-1
    const int o = idx >> 9;
    const int q = idx & 511;
    const uint4 w = pw4[idx];
    const float norm = __ldg(&norms[o * 32 + (q >> 4)]);

    __half2 h[4];
    h[0] = __floats2half2_rn(c[w.x & 15u] * norm, c[(w.x >> 4) & 15u] * norm);
    h[1] = __floats2half2_rn(c[w.y & 15u] * norm, c[(w.y >> 4) & 15u] * norm);
    h[2] = __floats2half2_rn(c[w.z & 15u] * norm, c[(w.z >> 4) & 15u] * norm);
    h[3] = __floats2half2_rn(c[w.w & 15u] * norm, c[(w.w >> 4) & 15u] * norm);

    const int nt = o >> 8, r = o & 255;
    const int kc = q >> 3;
    const uint32_t off = swz128((uint32_t)(r * 128 + (q & 7) * 16));
    const size_t base = ((size_t)nt * NKC + kc) * B_BLK_BYTES;
    *(uint4*)(Bt + base + off) = *(uint4*)h;
}

// ---------------------------------------------------------------------------
// Kernel 3: mma.sync GEMM — BYTE-IDENTICAL to the round-10 winner (862.5 us).
// No gating, no counters. The mainloop is FROZEN (R4/R11/R12 all regressed).
// ---------------------------------------------------------------------------
extern __shared__ unsigned char dsm[];

template <int NBW>   // MMAs along N per warp: 8 (full) or 4 (half)
__device__ __forceinline__ void consume_tile(
    uint32_t sb, float* __restrict__ C, const float* __restrict__ bias,
    int bm, int bn, int wid, int lane) {
    const int wm = (wid >> 2) * 64;
    const int wn = (wid & 3) * (NBW * 8);

    float acc[4][NBW][4];
#pragma unroll
    for (int i = 0; i < 4; i++)
#pragma unroll
        for (int j = 0; j < NBW; j++)
#pragma unroll
            for (int k = 0; k < 4; k++) acc[i][j][k] = 0.0f;

    const int a_row = lane & 15;
    const int a_colh = (lane >> 4) * 8;
    const int b_row = (lane & 7) + (lane >> 4) * 8;
    const int b_colh = ((lane >> 3) & 1) * 8;

    for (int j = 0; j < NKC; j++) {
        const int s = j & 3;
        MBAR_WAIT(sb + 8 * s, (j >> 2) & 1);
        const uint32_t as = sb + 1024 + s * STAGE_BYTES;
        const uint32_t bs = as + A_BLK_BYTES;

#pragma unroll
        for (int ks = 0; ks < 4; ks++) {
            uint32_t afr[4][4];
#pragma unroll
            for (int m = 0; m < 4; m++)
                ldsm4(afr[m], as + swz128((uint32_t)((wm + m * 16 + a_row) * 128 +
                                                     (ks * 16 + a_colh) * 2)));
            uint32_t bfr[NBW / 2][4];
#pragma unroll
            for (int nb = 0; nb < NBW / 2; nb++)
                ldsm4(bfr[nb], bs + swz128((uint32_t)((wn + nb * 16 + b_row) * 128 +
                                                      (ks * 16 + b_colh) * 2)));
#pragma unroll
            for (int m = 0; m < 4; m++) {
#pragma unroll
                for (int n = 0; n < NBW; n++) {
                    mma16816(acc[m][n], afr[m], bfr[n >> 1][(n & 1) * 2],
                             bfr[n >> 1][(n & 1) * 2 + 1]);
                }
            }
        }
        if (lane == 0) MBAR_ARRIVE(sb + 32 + 8 * s);
    }

    // epilogue
    const int gid = lane >> 2;
    const int tq = lane & 3;
    float bz[NBW][2];
#pragma unroll
    for (int n = 0; n < NBW; n++) {
        const int col0 = bn + wn + n * 8 + tq * 2;
        bz[n][0] = __ldg(&bias[col0]);
        bz[n][1] = __ldg(&bias[col0 + 1]);
    }
#pragma unroll
    for (int m = 0; m < 4; m++) {
        const int row0 = bm + wm + m * 16 + gid;
#pragma unroll
        for (int n = 0; n < NBW; n++) {
            const int col0 = bn + wn + n * 8 + tq * 2;
            float2 v0 = { acc[m][n][0] + bz[n][0], acc[m][n][1] + bz[n][1] };
            float2 v1 = { acc[m][n][2] + bz[n][0], acc[m][n][3] + bz[n][1] };
            *(float2*)(C + (size_t)row0 * N_DIM + col0) = v0;
            *(float2*)(C + (size_t)(row0 + 8) * N_DIM + col0) = v1;
        }
    }
}

__global__ __launch_bounds__(288, 1) void gemm_kernel(
    const unsigned char* __restrict__ At, const unsigned char* __restrict__ Bt,
    const float* __restrict__ bias, float* __restrict__ C) {
    const int tid = threadIdx.x;
    const int wid = tid >> 5;
    const int lane = tid & 31;
    const uint32_t sb = (smem_u32(dsm) + 1023) & ~1023u;

    // id -> (mt, nt, half). nt-fastest order; last 44 tiles split into N-halves.
    const int id = blockIdx.x;
    int mt, nt, half;
    if (id < FULL_CTAS) {
        mt = id / NNT; nt = id - mt * NNT; half = -1;
    } else {
        const int k = id - FULL_CTAS;             // 0..87
        const int tile = FULL_CTAS + (k >> 1);    // 1332..1375
        mt = tile / NNT; nt = tile - mt * NNT; half = k & 1;
    }
    const unsigned char* Ag = At + (size_t)mt * NKC * A_BLK_BYTES;
    const unsigned char* Bg = Bt + (size_t)nt * NKC * B_BLK_BYTES +
                              (half > 0 ? 16384 : 0);
    const uint32_t bsz = (half < 0) ? 32768u : 16384u;
    const int bm = mt * BM;
    const int bn = nt * BN + (half > 0 ? 128 : 0);

    if (tid == 0) {
#pragma unroll
        for (int s = 0; s < NSTAGES; s++) {
            MBAR_INIT(sb + 8 * s, 1);       // full[s]
            MBAR_INIT(sb + 32 + 8 * s, 8);  // empty[s]
        }
        asm volatile("fence.proxy.async.shared::cta;" ::: "memory");
    }
    __syncthreads();

    if (wid == 8) {
        // ---------------- producer warp (lane 0 only) ----------------
        if (lane == 0) {
            for (int j = 0; j < NKC; j++) {
                const int s = j & 3;
                if (j >= NSTAGES) {
                    MBAR_WAIT(sb + 32 + 8 * s, ((j >> 2) - 1) & 1);
                }
                const uint32_t full = sb + 8 * s;
                MBAR_EXPECT_TX(full, A_BLK_BYTES + bsz);
                const uint32_t st = sb + 1024 + s * STAGE_BYTES;
                bulk_ld(st, Ag + (size_t)j * A_BLK_BYTES, A_BLK_BYTES, full);
                bulk_ld(st + A_BLK_BYTES, Bg + (size_t)j * B_BLK_BYTES, bsz, full);
            }
        }
        return;
    }

    if (half < 0) consume_tile<8>(sb, C, bias, bm, bn, wid, lane);
    else          consume_tile<4>(sb, C, bias, bm, bn, wid, lane);
}

// ---------------------------------------------------------------------------
// Launch: fork/join with the join BEFORE the GEMM — dequant (side stream)
// overlaps ONLY transform_x (prep with prep, not prep with GEMM):
//   stream 0 : (fork evF) transform_x ── waits evJ ── gemm
//   stream s2: (waits evF) dequant ── records evJ
// ---------------------------------------------------------------------------
extern "C" void kernel_launch(void* const* d_in, const int* in_sizes, int n_in,
                              void* d_out, int out_size) {
    const float* x     = (const float*)d_in[0];
    const uint4* pw4   = (const uint4*)d_in[1];
    const float* norms = (const float*)d_in[2];
    const float* cent  = (const float*)d_in[3];
    const float* s1    = (const float*)d_in[4];
    const float* s2v   = (const float*)d_in[5];
    const float* bias  = (const float*)d_in[6];
    float* out = (float*)d_out;

    unsigned char *At, *Bt;
    cudaGetSymbolAddress((void**)&At, g_A);
    cudaGetSymbolAddress((void**)&Bt, g_B);

    static cudaStream_t s2 = nullptr;
    static cudaEvent_t evF = nullptr, evJ = nullptr;
    if (s2 == nullptr) {
        cudaStreamCreateWithFlags(&s2, cudaStreamNonBlocking);
        cudaEventCreateWithFlags(&evF, cudaEventDisableTiming);
        cudaEventCreateWithFlags(&evJ, cudaEventDisableTiming);
        cudaFuncSetAttribute(gemm_kernel, cudaFuncAttributeMaxDynamicSharedMemorySize,
                             SM_TOTAL);
    }

    // fork: dequant on side stream, concurrent with transform_x on stream 0
    cudaEventRecord(evF, 0);
    cudaStreamWaitEvent(s2, evF, 0);
    dequant_kernel<<<DQ_BLOCKS, 256, 0, s2>>>(pw4, norms, cent, Bt);
    cudaEventRecord(evJ, s2);

    transform_x_kernel<<<TX_BLOCKS, 256>>>(x, s1, s2v, At);

    // join BEFORE the GEMM: B fully written, GEMM runs uncontended
    cudaStreamWaitEvent(0, evJ, 0);
    gemm_kernel<<<GRID_CTAS, 288, SM_TOTAL>>>(At, Bt, bias, out);
}

// round 16
// speedup vs baseline: 1.0183x; 1.0039x over previous
#include <cuda_runtime.h>
#include <cuda_fp16.h>
#include <cstdint>

// ---------------------------------------------------------------------------
// Problem constants
// ---------------------------------------------------------------------------
#define M_DIM 4096
#define N_DIM 11008
#define K_DIM 4096
#define GROUP 128

#define BM 128            // CTA M tile
#define BN 256            // CTA N tile (full tiles)
#define KC 64             // K halves per pipeline chunk (= 128 bytes per row)
#define NKC (K_DIM / KC)  // 64 chunks
#define NMT (M_DIM / BM)  // 32
#define NNT (N_DIM / BN)  // 43

#define A_BLK_BYTES (BM * 128)       // 16384
#define B_BLK_BYTES (BN * 128)       // 32768
#define STAGE_BYTES (A_BLK_BYTES + B_BLK_BYTES)  // 49152
#define NSTAGES 4
#define SM_TOTAL (2048 + NSTAGES * STAGE_BYTES)  // 198656

// Wave-quantization split: 1332 full tiles (9 exact waves of 148) + the last
// 44 tiles split into 88 N-halves forming a short final wave.
#define FULL_CTAS 1332
#define GRID_CTAS (FULL_CTAS + 88)   // 1420

// Merged prep: 22016 dequant + 8192 transform blocks, interleaved with
// period 59 (43 dq : 16 tx — exact ratio, 59*512 = 30208 total).
#define DQ_BLOCKS 22016
#define TX_BLOCKS 8192
#define PREP_BLOCKS (DQ_BLOCKS + TX_BLOCKS)   // 30208

// Tiled+swizzled scratch in GMEM
__device__ uint4 g_A[(size_t)NMT * NKC * A_BLK_BYTES / 16];   // 33.5 MB
__device__ uint4 g_B[(size_t)NNT * NKC * B_BLK_BYTES / 16];   // 90.2 MB

__host__ __device__ __forceinline__ uint32_t swz128(uint32_t off) {
    return off ^ ((off >> 3) & 0x70u);
}

// ---------------------------------------------------------------------------
// PTX helpers (sm_90-level only; tcgen05 NOT available in this build path)
// ---------------------------------------------------------------------------
__device__ __forceinline__ uint32_t smem_u32(const void* p) {
    uint32_t a;
    asm("{ .reg .u64 t; cvta.to.shared.u64 t, %1; cvt.u32.u64 %0, t; }" : "=r"(a) : "l"(p));
    return a;
}

#define MBAR_INIT(addr, cnt) \
    asm volatile("mbarrier.init.shared.b64 [%0], %1;" :: "r"(addr), "r"(cnt) : "memory")

#define MBAR_EXPECT_TX(addr, bytes) \
    asm volatile("mbarrier.arrive.expect_tx.shared.b64 _, [%0], %1;" :: "r"(addr), "r"(bytes) : "memory")

#define MBAR_ARRIVE(addr) \
    asm volatile("mbarrier.arrive.shared.b64 _, [%0];" :: "r"(addr) : "memory")

#define MBAR_WAIT(addr, parity) do {                                        \
    uint32_t _m = (addr); uint32_t _p = (parity); uint32_t _d;              \
    asm volatile("{\n\t.reg .pred p;\n\t"                                   \
        "mbarrier.try_wait.parity.acquire.cta.shared::cta.b64 p, [%1], %2;\n\t" \
        "selp.b32 %0, 1, 0, p;\n\t}"                                        \
        : "=r"(_d) : "r"(_m), "r"(_p) : "memory");                          \
    if (!_d) {                                                              \
        asm volatile("{\n\t.reg .pred P1;\n\t"                              \
            "W0_%=:\n\t"                                                    \
            "mbarrier.try_wait.parity.acquire.cta.shared::cta.b64 P1, [%0], %1, 0x989680;\n\t" \
            "@P1 bra.uni W1_%=;\n\t"                                        \
            "bra.uni W0_%=;\n\t"                                            \
            "W1_%=:\n\t}" :: "r"(_m), "r"(_p) : "memory");                  \
    }                                                                       \
} while (0)

__device__ __forceinline__ void bulk_ld(uint32_t dst, const void* src, uint32_t bytes,
                                        uint32_t mbar) {
    asm volatile(
        "cp.async.bulk.shared::cluster.global.mbarrier::complete_tx::bytes [%0], [%1], %2, [%3];"
        :: "r"(dst), "l"(src), "r"(bytes), "r"(mbar) : "memory");
}

__device__ __forceinline__ void ldsm4(uint32_t* r, uint32_t addr) {
    asm volatile("ldmatrix.sync.aligned.m8n8.x4.shared.b16 {%0,%1,%2,%3}, [%4];\n"
                 : "=r"(r[0]), "=r"(r[1]), "=r"(r[2]), "=r"(r[3]) : "r"(addr));
}
__device__ __forceinline__ void mma16816(float* c, const uint32_t* a, uint32_t b0, uint32_t b1) {
    asm volatile(
        "mma.sync.aligned.m16n8k16.row.col.f32.f16.f16.f32 "
        "{%0,%1,%2,%3}, {%4,%5,%6,%7}, {%8,%9}, {%0,%1,%2,%3};\n"
        : "+f"(c[0]), "+f"(c[1]), "+f"(c[2]), "+f"(c[3])
        : "r"(a[0]), "r"(a[1]), "r"(a[2]), "r"(a[3]), "r"(b0), "r"(b1));
}

// ---------------------------------------------------------------------------
// Kernel 1 (merged prep, period-59 interleave): r = b%59 < 43 -> dequant block
// q*43+r, else transform block q*16+(r-43). Both branches byte-equivalent to
// the round-10 measured kernels; only the block->work mapping changed so the
// two populations are RESIDENT SIMULTANEOUSLY (dequant is DRAM-bound at 60%,
// transform is issue-bound at 31% DRAM -> they share the chip).
// ---------------------------------------------------------------------------
__global__ __launch_bounds__(256) void prep_kernel(
    const float* __restrict__ x, const float* __restrict__ s1,
    const float* __restrict__ s2, unsigned char* __restrict__ At,
    const uint4* __restrict__ pw4, const float* __restrict__ norms,
    const float* __restrict__ cent, unsigned char* __restrict__ Bt) {
    const int q = blockIdx.x / 59;
    const int r59 = blockIdx.x - q * 59;

    if (r59 < 43) {
        // ---------------- dequant W (block id = q*43 + r59) ----------------
        __shared__ float c[16];
        if (threadIdx.x < 16) c[threadIdx.x] = cent[threadIdx.x];
        __syncthreads();

        const int blk = q * 43 + r59;                  // 0 .. 22015
        const int idx = blk * 256 + threadIdx.x;       // 0 .. 11008*512-1
        const int o = idx >> 9;
        const int qq = idx & 511;
        const uint4 w = pw4[idx];
        const float norm = __ldg(&norms[o * 32 + (qq >> 4)]);

        __half2 h[4];
        h[0] = __floats2half2_rn(c[w.x & 15u] * norm, c[(w.x >> 4) & 15u] * norm);
        h[1] = __floats2half2_rn(c[w.y & 15u] * norm, c[(w.y >> 4) & 15u] * norm);
        h[2] = __floats2half2_rn(c[w.z & 15u] * norm, c[(w.z >> 4) & 15u] * norm);
        h[3] = __floats2half2_rn(c[w.w & 15u] * norm, c[(w.w >> 4) & 15u] * norm);

        const int nt = o >> 8, rr = o & 255;
        const int kc = qq >> 3;
        const uint32_t off = swz128((uint32_t)(rr * 128 + (qq & 7) * 16));
        const size_t base = ((size_t)nt * NKC + kc) * B_BLK_BYTES;
        *(uint4*)(Bt + base + off) = *(uint4*)h;
    } else {
        // ---------------- transform x (block id = q*16 + r59-43) ----------------
        const int blk = q * 16 + (r59 - 43);           // 0 .. 8191
        const int lane = threadIdx.x & 31;
        const int wrp = threadIdx.x >> 5;
        const int unit = blk * 8 + wrp;                // 0 .. 65535
        const int row = unit >> 4;
        const int g0 = (unit & 15) * 2;

        const float4 s1v = *(const float4*)(s1 + lane * 4);
        const float4 s2v = *(const float4*)(s2 + lane * 4);

        float v[8];
        {
            const float4 a = *(const float4*)(x + (size_t)row * K_DIM + g0 * GROUP + lane * 4);
            const float4 b = *(const float4*)(x + (size_t)row * K_DIM + (g0 + 1) * GROUP + lane * 4);
            v[0] = a.x * s1v.x; v[1] = a.y * s1v.y; v[2] = a.z * s1v.z; v[3] = a.w * s1v.w;
            v[4] = b.x * s1v.x; v[5] = b.y * s1v.y; v[6] = b.z * s1v.z; v[7] = b.w * s1v.w;
        }

#pragma unroll
        for (int pass = 0; pass < 2; pass++) {
#pragma unroll
            for (int h = 0; h < 2; h++) {
                float t0 = v[h*4+0] + v[h*4+1], t1 = v[h*4+0] - v[h*4+1];
                float t2 = v[h*4+2] + v[h*4+3], t3 = v[h*4+2] - v[h*4+3];
                v[h*4+0] = t0 + t2; v[h*4+2] = t0 - t2;
                v[h*4+1] = t1 + t3; v[h*4+3] = t1 - t3;
            }
#pragma unroll
            for (int xm = 1; xm <= 16; xm <<= 1) {
                bool hi = (lane & xm) != 0;
#pragma unroll
                for (int j = 0; j < 8; j++) {
                    float o = __shfl_xor_sync(0xFFFFFFFFu, v[j], xm);
                    v[j] = hi ? (o - v[j]) : (v[j] + o);
                }
            }
            if (pass == 0) {
                v[0] *= s2v.x; v[1] *= s2v.y; v[2] *= s2v.z; v[3] *= s2v.w;
                v[4] *= s2v.x; v[5] *= s2v.y; v[6] *= s2v.z; v[7] *= s2v.w;
            }
        }

        const float sc = 1.0f / 128.0f;
        const int mt = row >> 7, rr = row & 127;
        const int e = 4 * lane;
#pragma unroll
        for (int h = 0; h < 2; h++) {
            __half2 h01 = __floats2half2_rn(v[h*4+0] * sc, v[h*4+1] * sc);
            __half2 h23 = __floats2half2_rn(v[h*4+2] * sc, v[h*4+3] * sc);
            const int grp = g0 + h;
            const int kc = grp * 2 + (e >> 6);
            const int c = e & 63;
            const size_t base = ((size_t)mt * NKC + kc) * A_BLK_BYTES;
            const uint32_t off = swz128((uint32_t)(rr * 128 + c * 2));
            uint2 val = { *(uint32_t*)&h01, *(uint32_t*)&h23 };
            *(uint2*)(At + base + off) = val;
        }
    }
}

// ---------------------------------------------------------------------------
// Kernel 2: mma.sync GEMM — BYTE-IDENTICAL to the round-10 winner (862.5 us).
// The mainloop is FROZEN (R4/R11/R12 structural edits all regressed).
// Schedule floor proven at 9.5 tile-units (~802 us); measured 810.9.
// ---------------------------------------------------------------------------
extern __shared__ unsigned char dsm[];

template <int NBW>   // MMAs along N per warp: 8 (full) or 4 (half)
__device__ __forceinline__ void consume_tile(
    uint32_t sb, float* __restrict__ C, const float* __restrict__ bias,
    int bm, int bn, int wid, int lane) {
    const int wm = (wid >> 2) * 64;
    const int wn = (wid & 3) * (NBW * 8);

    float acc[4][NBW][4];
#pragma unroll
    for (int i = 0; i < 4; i++)
#pragma unroll
        for (int j = 0; j < NBW; j++)
#pragma unroll
            for (int k = 0; k < 4; k++) acc[i][j][k] = 0.0f;

    const int a_row = lane & 15;
    const int a_colh = (lane >> 4) * 8;
    const int b_row = (lane & 7) + (lane >> 4) * 8;
    const int b_colh = ((lane >> 3) & 1) * 8;

    for (int j = 0; j < NKC; j++) {
        const int s = j & 3;
        MBAR_WAIT(sb + 8 * s, (j >> 2) & 1);
        const uint32_t as = sb + 1024 + s * STAGE_BYTES;
        const uint32_t bs = as + A_BLK_BYTES;

#pragma unroll
        for (int ks = 0; ks < 4; ks++) {
            uint32_t afr[4][4];
#pragma unroll
            for (int m = 0; m < 4; m++)
                ldsm4(afr[m], as + swz128((uint32_t)((wm + m * 16 + a_row) * 128 +
                                                     (ks * 16 + a_colh) * 2)));
            uint32_t bfr[NBW / 2][4];
#pragma unroll
            for (int nb = 0; nb < NBW / 2; nb++)
                ldsm4(bfr[nb], bs + swz128((uint32_t)((wn + nb * 16 + b_row) * 128 +
                                                      (ks * 16 + b_colh) * 2)));
#pragma unroll
            for (int m = 0; m < 4; m++) {
#pragma unroll
                for (int n = 0; n < NBW; n++) {
                    mma16816(acc[m][n], afr[m], bfr[n >> 1][(n & 1) * 2],
                             bfr[n >> 1][(n & 1) * 2 + 1]);
                }
            }
        }
        if (lane == 0) MBAR_ARRIVE(sb + 32 + 8 * s);
    }

    // epilogue
    const int gid = lane >> 2;
    const int tq = lane & 3;
    float bz[NBW][2];
#pragma unroll
    for (int n = 0; n < NBW; n++) {
        const int col0 = bn + wn + n * 8 + tq * 2;
        bz[n][0] = __ldg(&bias[col0]);
        bz[n][1] = __ldg(&bias[col0 + 1]);
    }
#pragma unroll
    for (int m = 0; m < 4; m++) {
        const int row0 = bm + wm + m * 16 + gid;
#pragma unroll
        for (int n = 0; n < NBW; n++) {
            const int col0 = bn + wn + n * 8 + tq * 2;
            float2 v0 = { acc[m][n][0] + bz[n][0], acc[m][n][1] + bz[n][1] };
            float2 v1 = { acc[m][n][2] + bz[n][0], acc[m][n][3] + bz[n][1] };
            *(float2*)(C + (size_t)row0 * N_DIM + col0) = v0;
            *(float2*)(C + (size_t)(row0 + 8) * N_DIM + col0) = v1;
        }
    }
}

__global__ __launch_bounds__(288, 1) void gemm_kernel(
    const unsigned char* __restrict__ At, const unsigned char* __restrict__ Bt,
    const float* __restrict__ bias, float* __restrict__ C) {
    const int tid = threadIdx.x;
    const int wid = tid >> 5;
    const int lane = tid & 31;
    const uint32_t sb = (smem_u32(dsm) + 1023) & ~1023u;

    // id -> (mt, nt, half). nt-fastest order; last 44 tiles split into N-halves.
    const int id = blockIdx.x;
    int mt, nt, half;
    if (id < FULL_CTAS) {
        mt = id / NNT; nt = id - mt * NNT; half = -1;
    } else {
        const int k = id - FULL_CTAS;             // 0..87
        const int tile = FULL_CTAS + (k >> 1);    // 1332..1375
        mt = tile / NNT; nt = tile - mt * NNT; half = k & 1;
    }
    const unsigned char* Ag = At + (size_t)mt * NKC * A_BLK_BYTES;
    const unsigned char* Bg = Bt + (size_t)nt * NKC * B_BLK_BYTES +
                              (half > 0 ? 16384 : 0);
    const uint32_t bsz = (half < 0) ? 32768u : 16384u;
    const int bm = mt * BM;
    const int bn = nt * BN + (half > 0 ? 128 : 0);

    if (tid == 0) {
#pragma unroll
        for (int s = 0; s < NSTAGES; s++) {
            MBAR_INIT(sb + 8 * s, 1);       // full[s]
            MBAR_INIT(sb + 32 + 8 * s, 8);  // empty[s]
        }
        asm volatile("fence.proxy.async.shared::cta;" ::: "memory");
    }
    __syncthreads();

    if (wid == 8) {
        // ---------------- producer warp (lane 0 only) ----------------
        if (lane == 0) {
            for (int j = 0; j < NKC; j++) {
                const int s = j & 3;
                if (j >= NSTAGES) {
                    MBAR_WAIT(sb + 32 + 8 * s, ((j >> 2) - 1) & 1);
                }
                const uint32_t full = sb + 8 * s;
                MBAR_EXPECT_TX(full, A_BLK_BYTES + bsz);
                const uint32_t st = sb + 1024 + s * STAGE_BYTES;
                bulk_ld(st, Ag + (size_t)j * A_BLK_BYTES, A_BLK_BYTES, full);
                bulk_ld(st + A_BLK_BYTES, Bg + (size_t)j * B_BLK_BYTES, bsz, full);
            }
        }
        return;
    }

    if (half < 0) consume_tile<8>(sb, C, bias, bm, bn, wid, lane);
    else          consume_tile<4>(sb, C, bias, bm, bn, wid, lane);
}

// ---------------------------------------------------------------------------
// Launch (single stream, no events): interleaved prep, then GEMM.
// ---------------------------------------------------------------------------
extern "C" void kernel_launch(void* const* d_in, const int* in_sizes, int n_in,
                              void* d_out, int out_size) {
    const float* x     = (const float*)d_in[0];
    const uint4* pw4   = (const uint4*)d_in[1];
    const float* norms = (const float*)d_in[2];
    const float* cent  = (const float*)d_in[3];
    const float* s1    = (const float*)d_in[4];
    const float* s2v   = (const float*)d_in[5];
    const float* bias  = (const float*)d_in[6];
    float* out = (float*)d_out;

    unsigned char *At, *Bt;
    cudaGetSymbolAddress((void**)&At, g_A);
    cudaGetSymbolAddress((void**)&Bt, g_B);

    prep_kernel<<<PREP_BLOCKS, 256>>>(x, s1, s2v, At, pw4, norms, cent, Bt);

    static bool attr_set = false;
    if (!attr_set) {
        cudaFuncSetAttribute(gemm_kernel, cudaFuncAttributeMaxDynamicSharedMemorySize,
                             SM_TOTAL);
        attr_set = true;
    }
    gemm_kernel<<<GRID_CTAS, 288, SM_TOTAL>>>(At, Bt, bias, out);
}